// round 8
// baseline (speedup 1.0000x reference)
#include <cuda_runtime.h>
#include <cuda_fp16.h>
#include <cstdint>
#include <cfloat>

// Problem constants (fixed shapes for PQHotShared)
#define K_HOT   16384
#define R_DIM   64
#define D_DIM   4096
#define K_CB    2048
#define D_SUB   16
#define N_SV_U  (K_HOT * R_DIM / D_SUB)   // 65536
#define N_SV_B  (R_DIM * D_DIM / D_SUB)   // 16384
#define N_SV    (N_SV_U + N_SV_B)         // 81920

// Scratch (device globals — no allocation allowed)
__device__ __half g_Af[K_HOT * R_DIM];          // A as fp16 [m][k]
__device__ __half g_Bf[D_DIM * R_DIM];          // B^T as fp16 [n][k]
// Hi-only packed codebook: per cw 8 words, pairs ordered [p0,p4,p1,p5,p2,p6,p3,p7]
__device__ uint32_t g_cbhi[K_CB * 8];
__device__ float    g_hn[K_CB];                 // 0.5*||cb||^2 (fp32 fmaf chain)
__device__ float2   g_partmax[8];               // per-prep-block {max||c||, max||cl||}
__device__ int      g_flag_cnt;
__device__ int      g_flag_list[N_SV];

#define SW128(b) ((b) ^ (((b) >> 3) & 0x70))

__device__ __forceinline__ uint32_t smem_u32(const void* p) {
    uint32_t a;
    asm("{ .reg .u64 t; cvta.to.shared.u64 t, %1; cvt.u32.u64 %0, t; }"
        : "=r"(a) : "l"(p));
    return a;
}

__device__ __forceinline__ void ldmatrix_x4(uint32_t* r, uint32_t addr) {
    asm volatile("ldmatrix.sync.aligned.m8n8.x4.shared.b16 {%0,%1,%2,%3}, [%4];"
                 : "=r"(r[0]), "=r"(r[1]), "=r"(r[2]), "=r"(r[3]) : "r"(addr));
}

__device__ __forceinline__ void mma_f16(float* c, const uint32_t* a,
                                        const uint32_t* b) {
    asm volatile(
        "mma.sync.aligned.m16n8k16.row.col.f32.f16.f16.f32 "
        "{%0,%1,%2,%3}, {%4,%5,%6,%7}, {%8,%9}, {%0,%1,%2,%3};"
        : "+f"(c[0]), "+f"(c[1]), "+f"(c[2]), "+f"(c[3])
        : "r"(a[0]), "r"(a[1]), "r"(a[2]), "r"(a[3]), "r"(b[0]), "r"(b[1]));
}

__device__ __forceinline__ uint32_t pack_h2(float a, float b) {
    __half2 h = __floats2half2_rn(a, b);   // a -> low half (even k)
    return *(uint32_t*)&h;
}

// ---------------------------------------------------------------------------
// Codebook prep: hi-fp16 pack, half-norms, per-block max{||c||, ||cl||}.
// ---------------------------------------------------------------------------
__global__ __launch_bounds__(256) void cb_prep_kernel(const float* __restrict__ cb)
{
    __shared__ float2 red[256];
    const int tid = threadIdx.x;
    if (blockIdx.x == 0 && tid == 0) g_flag_cnt = 0;

    int cw = blockIdx.x * 256 + tid;
    float v[D_SUB];
    float hn = 0.f, nl2 = 0.f;
    float hi[D_SUB];
    #pragma unroll
    for (int j = 0; j < D_SUB; ++j) {
        v[j] = cb[cw * D_SUB + j];
        hn = fmaf(v[j], v[j], hn);
        hi[j] = __half2float(__float2half_rn(v[j]));
        float l = v[j] - hi[j];
        nl2 = fmaf(l, l, nl2);
    }
    float hn_half = 0.5f * hn;
    g_hn[cw] = hn_half;

    uint32_t w[8];
    #pragma unroll
    for (int i = 0; i < 4; ++i) {
        w[2 * i]     = pack_h2(hi[2 * i],     hi[2 * i + 1]);
        w[2 * i + 1] = pack_h2(hi[2 * i + 8], hi[2 * i + 9]);
    }
    uint4* dst = (uint4*)&g_cbhi[cw * 8];
    dst[0] = make_uint4(w[0], w[1], w[2], w[3]);
    dst[1] = make_uint4(w[4], w[5], w[6], w[7]);

    red[tid] = make_float2(sqrtf(hn), sqrtf(nl2));
    __syncthreads();
    for (int s = 128; s > 0; s >>= 1) {
        if (tid < s) {
            red[tid].x = fmaxf(red[tid].x, red[tid + s].x);
            red[tid].y = fmaxf(red[tid].y, red[tid + s].y);
        }
        __syncthreads();
    }
    if (tid == 0) g_partmax[blockIdx.x] = red[0];
}

// ---------------------------------------------------------------------------
// Shortlist PQ argmin: hi-only fp16 mma scan + top-2 + certified bound.
// Unresolved rows appended to g_flag_list for exact fp32 fallback.
// Blocks [0,256): U rows; [256,320): B rows (written transposed).
// ---------------------------------------------------------------------------
#define QROWS 256
#define QCH   512

__device__ __forceinline__ void top2_pair(float va, float vb, int base,
                                          float& s1, int& i1, float& s2)
{
    float hi = fmaxf(va, vb), lo = fminf(va, vb);
    int ih = (vb > va) ? base + 1 : base;       // tie -> smaller idx
    s2 = fmaxf(s2, fminf(s1, hi));
    s2 = fmaxf(s2, lo);
    bool p = hi > s1;                           // tie keeps older (smaller idx)
    i1 = p ? ih : i1;
    s1 = fmaxf(s1, hi);
}

__global__ __launch_bounds__(256) void pq_argmin_kernel(
    const float* __restrict__ U, const float* __restrict__ B,
    const float* __restrict__ rsU, const float* __restrict__ rsB,
    const float* __restrict__ cb,
    __half* __restrict__ Af, __half* __restrict__ Btf)
{
    __shared__ uint32_t cb_sh[QCH * 8];        // 16 KB, stride-8 rows
    __shared__ float hn_sh[QCH];               // 2 KB
    __shared__ int idx_sh[QROWS];

    const int tid = threadIdx.x;
    const int warp = tid >> 5, lane = tid & 31;
    const int g = lane >> 2, t = lane & 3;
    const bool isU = blockIdx.x < 256;
    const int svbase = isU ? blockIdx.x * QROWS : (blockIdx.x - 256) * QROWS;
    const float* Wp = isU ? U : B;

    // global norm maxima
    float maxC = 0.f, maxCl = 0.f;
    #pragma unroll
    for (int i = 0; i < 8; ++i) {
        float2 pm = g_partmax[i];
        maxC = fmaxf(maxC, pm.x);
        maxCl = fmaxf(maxCl, pm.y);
    }

    // A fragments (hi fp16) + per-slot partial norms of gh, gl
    uint32_t ahi[2][4];
    float nh2[4], nl2[4];
    #pragma unroll
    for (int h = 0; h < 4; ++h) {
        const int mt = h >> 1, rh = h & 1;
        int r = svbase + warp * 32 + mt * 16 + rh * 8 + g;
        int off; float rsv;
        if (isU) { off = (r >> 2) * 64 + (r & 3) * 16;     rsv = rsU[r >> 2]; }
        else     { off = (r >> 8) * 4096 + (r & 255) * 16; rsv = rsB[r >> 8]; }
        float v0 = Wp[off + 2 * t]     / rsv;
        float v1 = Wp[off + 2 * t + 1] / rsv;
        float v2 = Wp[off + 8 + 2 * t]     / rsv;
        float v3 = Wp[off + 8 + 2 * t + 1] / rsv;
        float h0 = __half2float(__float2half_rn(v0));
        float h1 = __half2float(__float2half_rn(v1));
        float h2 = __half2float(__float2half_rn(v2));
        float h3 = __half2float(__float2half_rn(v3));
        ahi[mt][rh]     = pack_h2(h0, h1);
        ahi[mt][2 + rh] = pack_h2(h2, h3);
        float l0 = v0 - h0, l1 = v1 - h1, l2 = v2 - h2, l3 = v3 - h3;
        nh2[h] = fmaf(h0, h0, fmaf(h1, h1, fmaf(h2, h2, h3 * h3)));
        nl2[h] = fmaf(l0, l0, fmaf(l1, l1, fmaf(l2, l2, l3 * l3)));
    }

    float bs1[4], bs2[4]; int bi1[4];
    #pragma unroll
    for (int q = 0; q < 4; ++q) { bs1[q] = -FLT_MAX; bs2[q] = -FLT_MAX; bi1[q] = 0; }

    for (int ch = 0; ch < K_CB; ch += QCH) {
        __syncthreads();
        {
            const uint4* src = (const uint4*)(g_cbhi + ch * 8);
            uint4* dst = (uint4*)cb_sh;
            #pragma unroll
            for (int it = 0; it < 4; ++it)
                dst[tid + it * 256] = src[tid + it * 256];
            hn_sh[tid] = g_hn[ch + tid];
            hn_sh[tid + 256] = g_hn[ch + tid + 256];
        }
        __syncthreads();

        #pragma unroll 4
        for (int nt = 0; nt < QCH / 8; ++nt) {
            const int n0 = nt * 8;
            uint2 bhp = *(const uint2*)&cb_sh[(n0 + g) * 8 + 2 * t];
            uint32_t bh[2] = {bhp.x, bhp.y};
            float2 hnp = *(const float2*)&hn_sh[n0 + 2 * t];
            const int base = ch + n0 + 2 * t;
            #pragma unroll
            for (int mt = 0; mt < 2; ++mt) {
                float c[4] = {-hnp.x, -hnp.y, -hnp.x, -hnp.y};
                mma_f16(c, ahi[mt], bh);
                top2_pair(c[0], c[1], base, bs1[mt * 2], bi1[mt * 2], bs2[mt * 2]);
                top2_pair(c[2], c[3], base, bs1[mt * 2 + 1], bi1[mt * 2 + 1], bs2[mt * 2 + 1]);
            }
        }
    }

    // Per-row reduction across the 4 t-lanes: top2 merge + norm sums + flag.
    #pragma unroll
    for (int q = 0; q < 4; ++q) {
        float s1 = bs1[q], s2 = bs2[q];
        int i1 = bi1[q];
        float a2 = nh2[q], b2 = nl2[q];
        #pragma unroll
        for (int d = 1; d <= 2; d <<= 1) {
            float os1 = __shfl_xor_sync(0xffffffffu, s1, d);
            int   oi1 = __shfl_xor_sync(0xffffffffu, i1, d);
            float os2 = __shfl_xor_sync(0xffffffffu, s2, d);
            a2 += __shfl_xor_sync(0xffffffffu, a2, d);
            b2 += __shfl_xor_sync(0xffffffffu, b2, d);
            float cand;
            if (os1 > s1 || (os1 == s1 && oi1 < i1)) { cand = s1; s1 = os1; i1 = oi1; }
            else cand = os1;
            s2 = fmaxf(fmaxf(s2, os2), cand);
        }
        if (t == 0) {
            const int rloc = warp * 32 + (q >> 1) * 16 + (q & 1) * 8 + g;
            idx_sh[rloc] = i1;
            float bound = sqrtf(b2) * maxC + sqrtf(a2) * maxCl + 1e-5f;
            if (s1 - s2 <= 2.f * bound) {
                int p = atomicAdd(&g_flag_cnt, 1);
                g_flag_list[p] = (isU ? 0 : N_SV_U) + svbase + rloc;
            }
        }
    }
    __syncwarp();

    // Dequant write: each lane owns one row of the warp's 32 (provisional for
    // flagged rows; fallback kernel overwrites those).
    {
        const int rloc = warp * 32 + lane;
        const int w = idx_sh[rloc];
        const int r = svbase + rloc;
        const float* cbr = cb + w * D_SUB;
        if (isU) {
            const int urow = r >> 2;
            const float rsv = rsU[urow];
            const int off = urow * 64 + (r & 3) * 16;
            uint32_t* df = (uint32_t*)(Af + off);
            #pragma unroll
            for (int p = 0; p < 8; ++p)
                df[p] = pack_h2(cbr[2 * p] * rsv, cbr[2 * p + 1] * rsv);
        } else {
            const int brow = r >> 8;
            const float rsv = rsB[brow];
            const int nb = (r & 255) * 16;
            #pragma unroll
            for (int j = 0; j < D_SUB; ++j)
                Btf[(nb + j) * 64 + brow] = __float2half_rn(cbr[j] * rsv);
        }
    }
}

// ---------------------------------------------------------------------------
// Exact fp32 fallback for unresolved rows (same math as the round-1 kernel
// that passed with rel_err 0.0). One warp per flagged row, work-stealing.
// ---------------------------------------------------------------------------
#define FB_CH 512

__global__ __launch_bounds__(128) void pq_fallback_kernel(
    const float* __restrict__ U, const float* __restrict__ B,
    const float* __restrict__ rsU, const float* __restrict__ rsB,
    const float* __restrict__ cb,
    __half* __restrict__ Af, __half* __restrict__ Btf)
{
    __shared__ float cb_f[FB_CH * 17];   // stride 17: conflict-free per-lane rows
    __shared__ float hn_f[FB_CH];

    const int tid = threadIdx.x;
    const int warp = tid >> 5, lane = tid & 31;
    const int cnt = g_flag_cnt;

    for (int it = blockIdx.x * 4; it < cnt; it += gridDim.x * 4) {
        const int slot = it + warp;
        const int enc = (slot < cnt) ? g_flag_list[slot] : -1;

        float gv[D_SUB];
        float rsv = 1.f;
        if (enc >= 0) {
            const float* p;
            if (enc < N_SV_U) {
                int r = enc; int urow = r >> 2;
                rsv = rsU[urow];
                p = U + urow * 64 + (r & 3) * 16;
            } else {
                int r = enc - N_SV_U; int brow = r >> 8;
                rsv = rsB[brow];
                p = B + brow * 4096 + (r & 255) * 16;
            }
            #pragma unroll
            for (int d = 0; d < D_SUB; ++d) gv[d] = p[d] / rsv;
        }

        float best = -FLT_MAX; int bidx = 0;
        for (int chb = 0; chb < K_CB; chb += FB_CH) {
            __syncthreads();
            for (int i = tid; i < FB_CH * D_SUB; i += 128) {
                int c = i >> 4, d = i & 15;
                cb_f[c * 17 + d] = cb[(chb + c) * D_SUB + d];
            }
            for (int i = tid; i < FB_CH; i += 128)
                hn_f[i] = g_hn[chb + i];
            __syncthreads();
            if (enc >= 0) {
                for (int c = lane; c < FB_CH; c += 32) {
                    float dot = 0.f;
                    #pragma unroll
                    for (int d = 0; d < D_SUB; ++d)
                        dot = fmaf(gv[d], cb_f[c * 17 + d], dot);
                    float sc = dot - hn_f[c];
                    if (sc > best) { best = sc; bidx = chb + c; }
                }
            }
        }

        // warp reduce, tie -> smaller idx
        #pragma unroll
        for (int d = 1; d < 32; d <<= 1) {
            float so = __shfl_xor_sync(0xffffffffu, best, d);
            int   io = __shfl_xor_sync(0xffffffffu, bidx, d);
            if (so > best || (so == best && io < bidx)) { best = so; bidx = io; }
        }

        if (enc >= 0 && lane == 0) {
            const float* cbr = cb + bidx * D_SUB;
            if (enc < N_SV_U) {
                int r = enc; int urow = r >> 2;
                const int off = urow * 64 + (r & 3) * 16;
                uint32_t* df = (uint32_t*)(Af + off);
                #pragma unroll
                for (int p2 = 0; p2 < 8; ++p2)
                    df[p2] = pack_h2(cbr[2 * p2] * rsv, cbr[2 * p2 + 1] * rsv);
            } else {
                int r = enc - N_SV_U; int brow = r >> 8;
                const int nb = (r & 255) * 16;
                #pragma unroll
                for (int j = 0; j < D_SUB; ++j)
                    Btf[(nb + j) * 64 + brow] = __float2half_rn(cbr[j] * rsv);
            }
        }
    }
}

// ---------------------------------------------------------------------------
// fp16 single-pass GEMM on mma.sync (verified round 7, unchanged):
// C[16384,4096] = Af @ Bf^T, fp32 acc.
// ---------------------------------------------------------------------------
#define OFF_AF 0
#define OFF_BF 16384
#define GEMM_SMEM (2 * 16384)

__device__ __forceinline__ void load_tile_128x64(
    char* smem, int off, const __half* __restrict__ src, int tid)
{
    #pragma unroll
    for (int it = 0; it < 4; ++it) {
        int i = tid + it * 256;
        int m = i >> 3, q = i & 7;
        uint32_t b = (uint32_t)(m * 128 + q * 16);
        *(uint4*)(smem + off + SW128(b)) = ((const uint4*)(src + m * 64))[q];
    }
}

__global__ __launch_bounds__(256, 2) void mma_gemm_kernel(
    const __half* __restrict__ Af, const __half* __restrict__ Bf,
    float* __restrict__ C)
{
    extern __shared__ char smem[];
    const uint32_t sbase = smem_u32(smem);
    const int tid = threadIdx.x;
    const int wid = tid >> 5, lane = tid & 31;
    const int row0 = blockIdx.y * 128;
    const int col0 = blockIdx.x * 128;

    load_tile_128x64(smem, OFF_AF, Af + (size_t)row0 * R_DIM, tid);
    load_tile_128x64(smem, OFF_BF, Bf + (size_t)col0 * R_DIM, tid);
    __syncthreads();

    const int warp_m = wid & 3;
    const int warp_n = wid >> 2;
    const int mbase = warp_m * 32;
    const int nbase = warp_n * 64;

    const int a_row = mbase + (lane & 15);
    const int a_kb  = (lane >> 4) * 16;
    const int b_nrow = nbase + (lane & 7) + (lane >> 4) * 8;
    const int b_kb   = ((lane >> 3) & 1) * 16;

    float acc[2][8][4];
    #pragma unroll
    for (int mt = 0; mt < 2; ++mt)
        #pragma unroll
        for (int nt = 0; nt < 8; ++nt)
            #pragma unroll
            for (int q = 0; q < 4; ++q) acc[mt][nt][q] = 0.f;

    #pragma unroll
    for (int k = 0; k < 4; ++k) {
        uint32_t a[2][4];
        #pragma unroll
        for (int mt = 0; mt < 2; ++mt) {
            uint32_t b = (uint32_t)((a_row + mt * 16) * 128 + k * 32 + a_kb);
            ldmatrix_x4(a[mt], sbase + OFF_AF + SW128(b));
        }
        uint32_t bf[8][2];
        #pragma unroll
        for (int np = 0; np < 4; ++np) {
            uint32_t b = (uint32_t)((b_nrow + np * 16) * 128 + k * 32 + b_kb);
            uint32_t r[4];
            ldmatrix_x4(r, sbase + OFF_BF + SW128(b));
            bf[np * 2][0] = r[0]; bf[np * 2][1] = r[1];
            bf[np * 2 + 1][0] = r[2]; bf[np * 2 + 1][1] = r[3];
        }
        #pragma unroll
        for (int mt = 0; mt < 2; ++mt)
            #pragma unroll
            for (int nt = 0; nt < 8; ++nt)
                mma_f16(acc[mt][nt], a[mt], bf[nt]);
    }

    const int g = lane >> 2, t = lane & 3;
    #pragma unroll
    for (int mt = 0; mt < 2; ++mt) {
        float* Cr0 = C + (size_t)(row0 + mbase + mt * 16 + g) * D_DIM + col0 + nbase;
        float* Cr1 = Cr0 + 8 * D_DIM;
        #pragma unroll
        for (int nt = 0; nt < 8; ++nt) {
            *(float2*)(Cr0 + nt * 8 + t * 2) =
                make_float2(acc[mt][nt][0], acc[mt][nt][1]);
            *(float2*)(Cr1 + nt * 8 + t * 2) =
                make_float2(acc[mt][nt][2], acc[mt][nt][3]);
        }
    }
}

// ---------------------------------------------------------------------------
extern "C" void kernel_launch(void* const* d_in, const int* in_sizes, int n_in,
                              void* d_out, int out_size)
{
    (void)in_sizes; (void)n_in; (void)out_size;
    const float* U   = (const float*)d_in[0];
    const float* B   = (const float*)d_in[1];
    const float* rsU = (const float*)d_in[2];
    const float* rsB = (const float*)d_in[3];
    const float* cb  = (const float*)d_in[4];
    float* out = (float*)d_out;

    __half *af, *bf;
    cudaGetSymbolAddress((void**)&af, g_Af);
    cudaGetSymbolAddress((void**)&bf, g_Bf);

    cb_prep_kernel<<<8, 256>>>(cb);
    pq_argmin_kernel<<<320, 256>>>(U, B, rsU, rsB, cb, af, bf);
    pq_fallback_kernel<<<256, 128>>>(U, B, rsU, rsB, cb, af, bf);

    cudaFuncSetAttribute(mma_gemm_kernel,
                         cudaFuncAttributeMaxDynamicSharedMemorySize, GEMM_SMEM);
    dim3 grid(D_DIM / 128, K_HOT / 128);
    mma_gemm_kernel<<<grid, 256, GEMM_SMEM>>>(af, bf, out);
}

// round 9
// speedup vs baseline: 1.0360x; 1.0360x over previous
#include <cuda_runtime.h>
#include <cuda_fp16.h>
#include <cstdint>
#include <cfloat>

// Problem constants (fixed shapes for PQHotShared)
#define K_HOT   16384
#define R_DIM   64
#define D_DIM   4096
#define K_CB    2048
#define D_SUB   16
#define N_SV_U  (K_HOT * R_DIM / D_SUB)   // 65536
#define N_SV_B  (R_DIM * D_DIM / D_SUB)   // 16384
#define N_SV    (N_SV_U + N_SV_B)         // 81920

// Scratch (device globals — no allocation allowed)
__device__ __half g_Af[K_HOT * R_DIM];          // A as fp16 [m][k]
__device__ __half g_Bf[D_DIM * R_DIM];          // B^T as fp16 [n][k]
// Hi-only packed codebook: per cw 8 words, pairs ordered [p0,p4,p1,p5,p2,p6,p3,p7]
__device__ uint32_t g_cbhi[K_CB * 8];
__device__ float    g_hn[K_CB];                 // 0.5*||cb||^2 (fp32 fmaf chain)
__device__ float2   g_partmax[8];               // per-prep-block {max||c||, max||cl||}
__device__ int      g_flag_cnt;
__device__ int      g_flag_list[N_SV];

#define SW128(b) ((b) ^ (((b) >> 3) & 0x70))

__device__ __forceinline__ uint32_t smem_u32(const void* p) {
    uint32_t a;
    asm("{ .reg .u64 t; cvta.to.shared.u64 t, %1; cvt.u32.u64 %0, t; }"
        : "=r"(a) : "l"(p));
    return a;
}

__device__ __forceinline__ void ldmatrix_x4(uint32_t* r, uint32_t addr) {
    asm volatile("ldmatrix.sync.aligned.m8n8.x4.shared.b16 {%0,%1,%2,%3}, [%4];"
                 : "=r"(r[0]), "=r"(r[1]), "=r"(r[2]), "=r"(r[3]) : "r"(addr));
}

__device__ __forceinline__ void mma_f16(float* c, const uint32_t* a,
                                        const uint32_t* b) {
    asm volatile(
        "mma.sync.aligned.m16n8k16.row.col.f32.f16.f16.f32 "
        "{%0,%1,%2,%3}, {%4,%5,%6,%7}, {%8,%9}, {%0,%1,%2,%3};"
        : "+f"(c[0]), "+f"(c[1]), "+f"(c[2]), "+f"(c[3])
        : "r"(a[0]), "r"(a[1]), "r"(a[2]), "r"(a[3]), "r"(b[0]), "r"(b[1]));
}

__device__ __forceinline__ uint32_t pack_h2(float a, float b) {
    __half2 h = __floats2half2_rn(a, b);   // a -> low half (even k)
    return *(uint32_t*)&h;
}

// ---------------------------------------------------------------------------
// Codebook prep: hi-fp16 pack, half-norms, per-block max{||c||, ||cl||}.
// ---------------------------------------------------------------------------
__global__ __launch_bounds__(256) void cb_prep_kernel(const float* __restrict__ cb)
{
    __shared__ float2 red[256];
    const int tid = threadIdx.x;
    if (blockIdx.x == 0 && tid == 0) g_flag_cnt = 0;

    int cw = blockIdx.x * 256 + tid;
    float v[D_SUB];
    float hn = 0.f, nl2 = 0.f;
    float hi[D_SUB];
    #pragma unroll
    for (int j = 0; j < D_SUB; ++j) {
        v[j] = cb[cw * D_SUB + j];
        hn = fmaf(v[j], v[j], hn);
        hi[j] = __half2float(__float2half_rn(v[j]));
        float l = v[j] - hi[j];
        nl2 = fmaf(l, l, nl2);
    }
    float hn_half = 0.5f * hn;
    g_hn[cw] = hn_half;

    uint32_t w[8];
    #pragma unroll
    for (int i = 0; i < 4; ++i) {
        w[2 * i]     = pack_h2(hi[2 * i],     hi[2 * i + 1]);
        w[2 * i + 1] = pack_h2(hi[2 * i + 8], hi[2 * i + 9]);
    }
    uint4* dst = (uint4*)&g_cbhi[cw * 8];
    dst[0] = make_uint4(w[0], w[1], w[2], w[3]);
    dst[1] = make_uint4(w[4], w[5], w[6], w[7]);

    red[tid] = make_float2(sqrtf(hn), sqrtf(nl2));
    __syncthreads();
    for (int s = 128; s > 0; s >>= 1) {
        if (tid < s) {
            red[tid].x = fmaxf(red[tid].x, red[tid + s].x);
            red[tid].y = fmaxf(red[tid].y, red[tid + s].y);
        }
        __syncthreads();
    }
    if (tid == 0) g_partmax[blockIdx.x] = red[0];
}

// ---------------------------------------------------------------------------
// Shortlist PQ argmin: hi-only fp16 mma scan + top-2 + certified bound.
// Unresolved rows appended to g_flag_list for exact fp32 fallback.
// Blocks [0,256): U rows; [256,320): B rows (written transposed).
// ---------------------------------------------------------------------------
#define QROWS 256
#define QCH   512

__device__ __forceinline__ void top2_pair(float va, float vb, int base,
                                          float& s1, int& i1, float& s2)
{
    float hi = fmaxf(va, vb), lo = fminf(va, vb);
    int ih = (vb > va) ? base + 1 : base;       // tie -> smaller idx
    s2 = fmaxf(s2, fminf(s1, hi));
    s2 = fmaxf(s2, lo);
    bool p = hi > s1;                           // tie keeps older (smaller idx)
    i1 = p ? ih : i1;
    s1 = fmaxf(s1, hi);
}

__global__ __launch_bounds__(256) void pq_argmin_kernel(
    const float* __restrict__ U, const float* __restrict__ B,
    const float* __restrict__ rsU, const float* __restrict__ rsB,
    const float* __restrict__ cb,
    __half* __restrict__ Af, __half* __restrict__ Btf)
{
    __shared__ uint32_t cb_sh[QCH * 8];        // 16 KB, stride-8 rows
    __shared__ float hn_sh[QCH];               // 2 KB
    __shared__ int idx_sh[QROWS];

    const int tid = threadIdx.x;
    const int warp = tid >> 5, lane = tid & 31;
    const int g = lane >> 2, t = lane & 3;
    const bool isU = blockIdx.x < 256;
    const int svbase = isU ? blockIdx.x * QROWS : (blockIdx.x - 256) * QROWS;
    const float* Wp = isU ? U : B;

    // global norm maxima
    float maxC = 0.f, maxCl = 0.f;
    #pragma unroll
    for (int i = 0; i < 8; ++i) {
        float2 pm = g_partmax[i];
        maxC = fmaxf(maxC, pm.x);
        maxCl = fmaxf(maxCl, pm.y);
    }

    // A fragments (hi fp16) + per-slot partial norms of gh, gl
    uint32_t ahi[2][4];
    float nh2[4], nl2[4];
    #pragma unroll
    for (int h = 0; h < 4; ++h) {
        const int mt = h >> 1, rh = h & 1;
        int r = svbase + warp * 32 + mt * 16 + rh * 8 + g;
        int off; float rsv;
        if (isU) { off = (r >> 2) * 64 + (r & 3) * 16;     rsv = rsU[r >> 2]; }
        else     { off = (r >> 8) * 4096 + (r & 255) * 16; rsv = rsB[r >> 8]; }
        float v0 = Wp[off + 2 * t]     / rsv;
        float v1 = Wp[off + 2 * t + 1] / rsv;
        float v2 = Wp[off + 8 + 2 * t]     / rsv;
        float v3 = Wp[off + 8 + 2 * t + 1] / rsv;
        float h0 = __half2float(__float2half_rn(v0));
        float h1 = __half2float(__float2half_rn(v1));
        float h2 = __half2float(__float2half_rn(v2));
        float h3 = __half2float(__float2half_rn(v3));
        ahi[mt][rh]     = pack_h2(h0, h1);
        ahi[mt][2 + rh] = pack_h2(h2, h3);
        float l0 = v0 - h0, l1 = v1 - h1, l2 = v2 - h2, l3 = v3 - h3;
        nh2[h] = fmaf(h0, h0, fmaf(h1, h1, fmaf(h2, h2, h3 * h3)));
        nl2[h] = fmaf(l0, l0, fmaf(l1, l1, fmaf(l2, l2, l3 * l3)));
    }

    float bs1[4], bs2[4]; int bi1[4];
    #pragma unroll
    for (int q = 0; q < 4; ++q) { bs1[q] = -FLT_MAX; bs2[q] = -FLT_MAX; bi1[q] = 0; }

    for (int ch = 0; ch < K_CB; ch += QCH) {
        __syncthreads();
        {
            const uint4* src = (const uint4*)(g_cbhi + ch * 8);
            uint4* dst = (uint4*)cb_sh;
            #pragma unroll
            for (int it = 0; it < 4; ++it)
                dst[tid + it * 256] = src[tid + it * 256];
            hn_sh[tid] = g_hn[ch + tid];
            hn_sh[tid + 256] = g_hn[ch + tid + 256];
        }
        __syncthreads();

        #pragma unroll 4
        for (int nt = 0; nt < QCH / 8; ++nt) {
            const int n0 = nt * 8;
            uint2 bhp = *(const uint2*)&cb_sh[(n0 + g) * 8 + 2 * t];
            uint32_t bh[2] = {bhp.x, bhp.y};
            float2 hnp = *(const float2*)&hn_sh[n0 + 2 * t];
            const int base = ch + n0 + 2 * t;
            #pragma unroll
            for (int mt = 0; mt < 2; ++mt) {
                float c[4] = {-hnp.x, -hnp.y, -hnp.x, -hnp.y};
                mma_f16(c, ahi[mt], bh);
                top2_pair(c[0], c[1], base, bs1[mt * 2], bi1[mt * 2], bs2[mt * 2]);
                top2_pair(c[2], c[3], base, bs1[mt * 2 + 1], bi1[mt * 2 + 1], bs2[mt * 2 + 1]);
            }
        }
    }

    // Per-row reduction across the 4 t-lanes: top2 merge + norm sums + flag.
    #pragma unroll
    for (int q = 0; q < 4; ++q) {
        float s1 = bs1[q], s2 = bs2[q];
        int i1 = bi1[q];
        float a2 = nh2[q], b2 = nl2[q];
        #pragma unroll
        for (int d = 1; d <= 2; d <<= 1) {
            float os1 = __shfl_xor_sync(0xffffffffu, s1, d);
            int   oi1 = __shfl_xor_sync(0xffffffffu, i1, d);
            float os2 = __shfl_xor_sync(0xffffffffu, s2, d);
            a2 += __shfl_xor_sync(0xffffffffu, a2, d);
            b2 += __shfl_xor_sync(0xffffffffu, b2, d);
            float cand;
            if (os1 > s1 || (os1 == s1 && oi1 < i1)) { cand = s1; s1 = os1; i1 = oi1; }
            else cand = os1;
            s2 = fmaxf(fmaxf(s2, os2), cand);
        }
        if (t == 0) {
            const int rloc = warp * 32 + (q >> 1) * 16 + (q & 1) * 8 + g;
            idx_sh[rloc] = i1;
            float bound = sqrtf(b2) * maxC + sqrtf(a2) * maxCl + 1e-5f;
            if (s1 - s2 <= 2.f * bound) {
                int p = atomicAdd(&g_flag_cnt, 1);
                g_flag_list[p] = (isU ? 0 : N_SV_U) + svbase + rloc;
            }
        }
    }
    __syncwarp();

    // Dequant write: each lane owns one row of the warp's 32 (provisional for
    // flagged rows; fallback kernel overwrites those).
    {
        const int rloc = warp * 32 + lane;
        const int w = idx_sh[rloc];
        const int r = svbase + rloc;
        const float* cbr = cb + w * D_SUB;
        if (isU) {
            const int urow = r >> 2;
            const float rsv = rsU[urow];
            const int off = urow * 64 + (r & 3) * 16;
            uint32_t* df = (uint32_t*)(Af + off);
            #pragma unroll
            for (int p = 0; p < 8; ++p)
                df[p] = pack_h2(cbr[2 * p] * rsv, cbr[2 * p + 1] * rsv);
        } else {
            const int brow = r >> 8;
            const float rsv = rsB[brow];
            const int nb = (r & 255) * 16;
            #pragma unroll
            for (int j = 0; j < D_SUB; ++j)
                Btf[(nb + j) * 64 + brow] = __float2half_rn(cbr[j] * rsv);
        }
    }
}

// ---------------------------------------------------------------------------
// Exact fp32 fallback: ONE WARP PER FLAGGED ROW, no smem, no barriers.
// Codebook (128 KB) is L2-resident; lanes stream it with LDG.128, stride-32
// codewords across lanes -> contiguous 2 KB warp segments, deep MLP.
// ---------------------------------------------------------------------------
__global__ __launch_bounds__(256) void pq_fallback_kernel(
    const float* __restrict__ U, const float* __restrict__ B,
    const float* __restrict__ rsU, const float* __restrict__ rsB,
    const float* __restrict__ cb,
    __half* __restrict__ Af, __half* __restrict__ Btf)
{
    const int cnt = g_flag_cnt;
    const int lane = threadIdx.x & 31;
    const int gwarp = (blockIdx.x * 256 + threadIdx.x) >> 5;
    const int nwarps = gridDim.x * 8;

    for (int slot = gwarp; slot < cnt; slot += nwarps) {
        const int enc = g_flag_list[slot];

        float gv[D_SUB];
        float rsv;
        {
            const float* p;
            if (enc < N_SV_U) {
                int r = enc; int urow = r >> 2;
                rsv = rsU[urow];
                p = U + urow * 64 + (r & 3) * 16;
            } else {
                int r = enc - N_SV_U; int brow = r >> 8;
                rsv = rsB[brow];
                p = B + brow * 4096 + (r & 255) * 16;
            }
            #pragma unroll
            for (int d = 0; d < D_SUB; ++d) gv[d] = p[d] / rsv;
        }

        float best = -FLT_MAX; int bidx = 0;
        #pragma unroll 4
        for (int c = lane; c < K_CB; c += 32) {
            const float4* cp = (const float4*)(cb + c * D_SUB);
            float4 w0 = cp[0], w1 = cp[1], w2 = cp[2], w3 = cp[3];
            float dot = 0.f;
            dot = fmaf(gv[0],  w0.x, dot); dot = fmaf(gv[1],  w0.y, dot);
            dot = fmaf(gv[2],  w0.z, dot); dot = fmaf(gv[3],  w0.w, dot);
            dot = fmaf(gv[4],  w1.x, dot); dot = fmaf(gv[5],  w1.y, dot);
            dot = fmaf(gv[6],  w1.z, dot); dot = fmaf(gv[7],  w1.w, dot);
            dot = fmaf(gv[8],  w2.x, dot); dot = fmaf(gv[9],  w2.y, dot);
            dot = fmaf(gv[10], w2.z, dot); dot = fmaf(gv[11], w2.w, dot);
            dot = fmaf(gv[12], w3.x, dot); dot = fmaf(gv[13], w3.y, dot);
            dot = fmaf(gv[14], w3.z, dot); dot = fmaf(gv[15], w3.w, dot);
            float sc = dot - g_hn[c];
            if (sc > best) { best = sc; bidx = c; }
        }

        // warp reduce, tie -> smaller idx
        #pragma unroll
        for (int d = 1; d < 32; d <<= 1) {
            float so = __shfl_xor_sync(0xffffffffu, best, d);
            int   io = __shfl_xor_sync(0xffffffffu, bidx, d);
            if (so > best || (so == best && io < bidx)) { best = so; bidx = io; }
        }

        if (lane == 0) {
            const float* cbr = cb + bidx * D_SUB;
            if (enc < N_SV_U) {
                int r = enc; int urow = r >> 2;
                const int off = urow * 64 + (r & 3) * 16;
                uint32_t* df = (uint32_t*)(Af + off);
                #pragma unroll
                for (int p2 = 0; p2 < 8; ++p2)
                    df[p2] = pack_h2(cbr[2 * p2] * rsv, cbr[2 * p2 + 1] * rsv);
            } else {
                int r = enc - N_SV_U; int brow = r >> 8;
                const int nb = (r & 255) * 16;
                #pragma unroll
                for (int j = 0; j < D_SUB; ++j)
                    Btf[(nb + j) * 64 + brow] = __float2half_rn(cbr[j] * rsv);
            }
        }
    }
}

// ---------------------------------------------------------------------------
// fp16 single-pass GEMM on mma.sync (verified rounds 7/8, unchanged):
// C[16384,4096] = Af @ Bf^T, fp32 acc.
// ---------------------------------------------------------------------------
#define OFF_AF 0
#define OFF_BF 16384
#define GEMM_SMEM (2 * 16384)

__device__ __forceinline__ void load_tile_128x64(
    char* smem, int off, const __half* __restrict__ src, int tid)
{
    #pragma unroll
    for (int it = 0; it < 4; ++it) {
        int i = tid + it * 256;
        int m = i >> 3, q = i & 7;
        uint32_t b = (uint32_t)(m * 128 + q * 16);
        *(uint4*)(smem + off + SW128(b)) = ((const uint4*)(src + m * 64))[q];
    }
}

__global__ __launch_bounds__(256, 2) void mma_gemm_kernel(
    const __half* __restrict__ Af, const __half* __restrict__ Bf,
    float* __restrict__ C)
{
    extern __shared__ char smem[];
    const uint32_t sbase = smem_u32(smem);
    const int tid = threadIdx.x;
    const int wid = tid >> 5, lane = tid & 31;
    const int row0 = blockIdx.y * 128;
    const int col0 = blockIdx.x * 128;

    load_tile_128x64(smem, OFF_AF, Af + (size_t)row0 * R_DIM, tid);
    load_tile_128x64(smem, OFF_BF, Bf + (size_t)col0 * R_DIM, tid);
    __syncthreads();

    const int warp_m = wid & 3;
    const int warp_n = wid >> 2;
    const int mbase = warp_m * 32;
    const int nbase = warp_n * 64;

    const int a_row = mbase + (lane & 15);
    const int a_kb  = (lane >> 4) * 16;
    const int b_nrow = nbase + (lane & 7) + (lane >> 4) * 8;
    const int b_kb   = ((lane >> 3) & 1) * 16;

    float acc[2][8][4];
    #pragma unroll
    for (int mt = 0; mt < 2; ++mt)
        #pragma unroll
        for (int nt = 0; nt < 8; ++nt)
            #pragma unroll
            for (int q = 0; q < 4; ++q) acc[mt][nt][q] = 0.f;

    #pragma unroll
    for (int k = 0; k < 4; ++k) {
        uint32_t a[2][4];
        #pragma unroll
        for (int mt = 0; mt < 2; ++mt) {
            uint32_t b = (uint32_t)((a_row + mt * 16) * 128 + k * 32 + a_kb);
            ldmatrix_x4(a[mt], sbase + OFF_AF + SW128(b));
        }
        uint32_t bf[8][2];
        #pragma unroll
        for (int np = 0; np < 4; ++np) {
            uint32_t b = (uint32_t)((b_nrow + np * 16) * 128 + k * 32 + b_kb);
            uint32_t r[4];
            ldmatrix_x4(r, sbase + OFF_BF + SW128(b));
            bf[np * 2][0] = r[0]; bf[np * 2][1] = r[1];
            bf[np * 2 + 1][0] = r[2]; bf[np * 2 + 1][1] = r[3];
        }
        #pragma unroll
        for (int mt = 0; mt < 2; ++mt)
            #pragma unroll
            for (int nt = 0; nt < 8; ++nt)
                mma_f16(acc[mt][nt], a[mt], bf[nt]);
    }

    const int g = lane >> 2, t = lane & 3;
    #pragma unroll
    for (int mt = 0; mt < 2; ++mt) {
        float* Cr0 = C + (size_t)(row0 + mbase + mt * 16 + g) * D_DIM + col0 + nbase;
        float* Cr1 = Cr0 + 8 * D_DIM;
        #pragma unroll
        for (int nt = 0; nt < 8; ++nt) {
            *(float2*)(Cr0 + nt * 8 + t * 2) =
                make_float2(acc[mt][nt][0], acc[mt][nt][1]);
            *(float2*)(Cr1 + nt * 8 + t * 2) =
                make_float2(acc[mt][nt][2], acc[mt][nt][3]);
        }
    }
}

// ---------------------------------------------------------------------------
extern "C" void kernel_launch(void* const* d_in, const int* in_sizes, int n_in,
                              void* d_out, int out_size)
{
    (void)in_sizes; (void)n_in; (void)out_size;
    const float* U   = (const float*)d_in[0];
    const float* B   = (const float*)d_in[1];
    const float* rsU = (const float*)d_in[2];
    const float* rsB = (const float*)d_in[3];
    const float* cb  = (const float*)d_in[4];
    float* out = (float*)d_out;

    __half *af, *bf;
    cudaGetSymbolAddress((void**)&af, g_Af);
    cudaGetSymbolAddress((void**)&bf, g_Bf);

    cb_prep_kernel<<<8, 256>>>(cb);
    pq_argmin_kernel<<<320, 256>>>(U, B, rsU, rsB, cb, af, bf);
    pq_fallback_kernel<<<296, 256>>>(U, B, rsU, rsB, cb, af, bf);

    cudaFuncSetAttribute(mma_gemm_kernel,
                         cudaFuncAttributeMaxDynamicSharedMemorySize, GEMM_SMEM);
    dim3 grid(D_DIM / 128, K_HOT / 128);
    mma_gemm_kernel<<<grid, 256, GEMM_SMEM>>>(af, bf, out);
}

// round 10
// speedup vs baseline: 1.3165x; 1.2708x over previous
#include <cuda_runtime.h>
#include <cuda_fp16.h>
#include <cstdint>
#include <cfloat>

// Problem constants (fixed shapes for PQHotShared)
#define K_HOT   16384
#define R_DIM   64
#define D_DIM   4096
#define K_CB    2048
#define D_SUB   16
#define N_SV_U  (K_HOT * R_DIM / D_SUB)   // 65536
#define N_SV_B  (R_DIM * D_DIM / D_SUB)   // 16384

// Scratch (device globals — no allocation allowed)
__device__ __half g_Af[K_HOT * R_DIM];          // A as fp16 [m][k]
__device__ __half g_Bf[D_DIM * R_DIM];          // B^T as fp16 [n][k]
// Packed codebook, fp16 hi/lo split. Per cw 16 words:
//   words 0..7 : hi pairs, order [p0,p4,p1,p5,p2,p6,p3,p7] (p_i = dims 2i,2i+1)
//   words 8..15: lo pairs, same order
__device__ uint32_t g_cbpack[K_CB * 16];
__device__ float    g_hn[K_CB];                 // 0.5*||cb||^2

#define SW128(b) ((b) ^ (((b) >> 3) & 0x70))

__device__ __forceinline__ uint32_t smem_u32(const void* p) {
    uint32_t a;
    asm("{ .reg .u64 t; cvta.to.shared.u64 t, %1; cvt.u32.u64 %0, t; }"
        : "=r"(a) : "l"(p));
    return a;
}

__device__ __forceinline__ void ldmatrix_x4(uint32_t* r, uint32_t addr) {
    asm volatile("ldmatrix.sync.aligned.m8n8.x4.shared.b16 {%0,%1,%2,%3}, [%4];"
                 : "=r"(r[0]), "=r"(r[1]), "=r"(r[2]), "=r"(r[3]) : "r"(addr));
}

__device__ __forceinline__ void mma_f16(float* c, const uint32_t* a,
                                        const uint32_t* b) {
    asm volatile(
        "mma.sync.aligned.m16n8k16.row.col.f32.f16.f16.f32 "
        "{%0,%1,%2,%3}, {%4,%5,%6,%7}, {%8,%9}, {%0,%1,%2,%3};"
        : "+f"(c[0]), "+f"(c[1]), "+f"(c[2]), "+f"(c[3])
        : "r"(a[0]), "r"(a[1]), "r"(a[2]), "r"(a[3]), "r"(b[0]), "r"(b[1]));
}

__device__ __forceinline__ uint32_t pack_h2(float a, float b) {
    __half2 h = __floats2half2_rn(a, b);   // a -> low half (even k)
    return *(uint32_t*)&h;
}

// ---------------------------------------------------------------------------
// Codebook prep: fp16 hi/lo split, packed for direct mma B-fragment loads,
// plus half squared norms (fp32).
// ---------------------------------------------------------------------------
__global__ __launch_bounds__(256) void cb_prep_kernel(const float* __restrict__ cb)
{
    int cw = blockIdx.x * 256 + threadIdx.x;
    if (cw >= K_CB) return;
    float v[D_SUB];
    float hn = 0.f;
    #pragma unroll
    for (int j = 0; j < D_SUB; ++j) {
        v[j] = cb[cw * D_SUB + j];
        hn = fmaf(v[j], v[j], hn);
    }
    g_hn[cw] = 0.5f * hn;

    float hi[D_SUB], lo[D_SUB];
    #pragma unroll
    for (int j = 0; j < D_SUB; ++j) {
        float h = __half2float(__float2half_rn(v[j]));
        hi[j] = h;
        lo[j] = v[j] - h;
    }
    uint32_t w[16];
    #pragma unroll
    for (int i = 0; i < 4; ++i) {
        int p0 = i, p1 = i + 4;
        w[2 * i]     = pack_h2(hi[2 * p0], hi[2 * p0 + 1]);
        w[2 * i + 1] = pack_h2(hi[2 * p1], hi[2 * p1 + 1]);
        w[8 + 2 * i]     = pack_h2(lo[2 * p0], lo[2 * p0 + 1]);
        w[8 + 2 * i + 1] = pack_h2(lo[2 * p1], lo[2 * p1 + 1]);
    }
    uint4* dst = (uint4*)&g_cbpack[cw * 16];
    #pragma unroll
    for (int q = 0; q < 4; ++q)
        dst[q] = make_uint4(w[4 * q], w[4 * q + 1], w[4 * q + 2], w[4 * q + 3]);
}

// ---------------------------------------------------------------------------
// Fused PQ argmin via fp16-split m16n8k16 mma (round-7 math, exact same
// selections) restructured for occupancy: one m16 tile per warp, 128 rows
// per block, 640 blocks. Blocks [0,512): U rows; [512,640): B rows
// (written transposed).
// ---------------------------------------------------------------------------
#define QROWS 128
#define QCH   512
#define QST   24          // words per codeword row in smem (conflict-free)

__global__ __launch_bounds__(256) void pq_argmin_kernel(
    const float* __restrict__ U, const float* __restrict__ B,
    const float* __restrict__ rsU, const float* __restrict__ rsB,
    const float* __restrict__ cb,
    __half* __restrict__ Af, __half* __restrict__ Btf)
{
    __shared__ uint32_t cb_sh[QCH * QST];       // 48 KB
    __shared__ float hn_sh[QCH];                // 2 KB
    __shared__ int idx_sh[QROWS];

    const int tid = threadIdx.x;
    const int warp = tid >> 5, lane = tid & 31;
    const int g = lane >> 2, t = lane & 3;
    const bool isU = blockIdx.x < 512;
    const int svbase = isU ? blockIdx.x * QROWS : (blockIdx.x - 512) * QROWS;
    const float* Wp = isU ? U : B;

    // A fragments (fp16 hi/lo), one m16 tile per warp:
    // a0=(row g, kp t), a1=(row g+8, kp t), a2=(row g, kp t+4), a3=(row g+8, kp t+4)
    uint32_t ahi[4], alo[4];
    #pragma unroll
    for (int rh = 0; rh < 2; ++rh) {
        int r = svbase + warp * 16 + rh * 8 + g;
        int off; float rsv;
        if (isU) { off = (r >> 2) * 64 + (r & 3) * 16;     rsv = rsU[r >> 2]; }
        else     { off = (r >> 8) * 4096 + (r & 255) * 16; rsv = rsB[r >> 8]; }
        float v0 = Wp[off + 2 * t]     / rsv;
        float v1 = Wp[off + 2 * t + 1] / rsv;
        float v2 = Wp[off + 8 + 2 * t]     / rsv;
        float v3 = Wp[off + 8 + 2 * t + 1] / rsv;
        float h0 = __half2float(__float2half_rn(v0));
        float h1 = __half2float(__float2half_rn(v1));
        float h2 = __half2float(__float2half_rn(v2));
        float h3 = __half2float(__float2half_rn(v3));
        ahi[rh]     = pack_h2(h0, h1);
        ahi[2 + rh] = pack_h2(h2, h3);
        alo[rh]     = pack_h2(v0 - h0, v1 - h1);
        alo[2 + rh] = pack_h2(v2 - h2, v3 - h3);
    }

    float bs[2]; int bi[2];
    #pragma unroll
    for (int q = 0; q < 2; ++q) { bs[q] = -FLT_MAX; bi[q] = 0; }

    for (int ch = 0; ch < K_CB; ch += QCH) {
        __syncthreads();
        {
            const uint4* src = (const uint4*)(g_cbpack + ch * 16);
            for (int i = tid; i < QCH * 4; i += 256) {
                int cw = i >> 2, q = i & 3;
                *(uint4*)&cb_sh[cw * QST + q * 4] = src[i];
            }
            for (int i = tid; i < QCH; i += 256)
                hn_sh[i] = g_hn[ch + i];
        }
        __syncthreads();

        #pragma unroll 4
        for (int nt = 0; nt < QCH / 8; ++nt) {
            const int n0 = nt * 8;
            const uint32_t* cwp = &cb_sh[(n0 + g) * QST];
            uint2 bhp = *(const uint2*)(cwp + 2 * t);        // (h_t, h_{t+4})
            uint2 blp = *(const uint2*)(cwp + 8 + 2 * t);    // (l_t, l_{t+4})
            uint32_t bh[2] = {bhp.x, bhp.y};
            uint32_t bl[2] = {blp.x, blp.y};
            float2 hnp = *(const float2*)&hn_sh[n0 + 2 * t];
            const int base = ch + n0 + 2 * t;
            float c[4] = {-hnp.x, -hnp.y, -hnp.x, -hnp.y};
            mma_f16(c, ahi, bh);
            mma_f16(c, ahi, bl);
            mma_f16(c, alo, bh);
            if (c[0] > bs[0]) { bs[0] = c[0]; bi[0] = base; }
            if (c[1] > bs[0]) { bs[0] = c[1]; bi[0] = base + 1; }
            if (c[2] > bs[1]) { bs[1] = c[2]; bi[1] = base; }
            if (c[3] > bs[1]) { bs[1] = c[3]; bi[1] = base + 1; }
        }
    }

    // Reduce argmax across the 4 t-lanes of each row quad (tie -> smaller idx)
    #pragma unroll
    for (int q = 0; q < 2; ++q) {
        float s = bs[q]; int i0 = bi[q];
        #pragma unroll
        for (int d = 1; d <= 2; d <<= 1) {
            float so = __shfl_xor_sync(0xffffffffu, s, d);
            int   io = __shfl_xor_sync(0xffffffffu, i0, d);
            if (so > s || (so == s && io < i0)) { s = so; i0 = io; }
        }
        if (t == 0)
            idx_sh[warp * 16 + q * 8 + g] = i0;
    }
    __syncwarp();

    // Dequant write: lanes 0..15 each own one row of the warp's 16.
    if (lane < 16) {
        const int rloc = warp * 16 + lane;
        const int w = idx_sh[rloc];
        const int r = svbase + rloc;
        const float* cbr = cb + w * D_SUB;
        if (isU) {
            const int urow = r >> 2;
            const float rsv = rsU[urow];
            const int off = urow * 64 + (r & 3) * 16;
            uint32_t* df = (uint32_t*)(Af + off);
            #pragma unroll
            for (int p = 0; p < 8; ++p)
                df[p] = pack_h2(cbr[2 * p] * rsv, cbr[2 * p + 1] * rsv);
        } else {
            const int brow = r >> 8;
            const float rsv = rsB[brow];
            const int nb = (r & 255) * 16;
            #pragma unroll
            for (int j = 0; j < D_SUB; ++j)
                Btf[(nb + j) * 64 + brow] = __float2half_rn(cbr[j] * rsv);
        }
    }
}

// ---------------------------------------------------------------------------
// fp16 single-pass GEMM on mma.sync (verified rounds 7-9, unchanged):
// C[16384,4096] = Af @ Bf^T, fp32 acc.
// ---------------------------------------------------------------------------
#define OFF_AF 0
#define OFF_BF 16384
#define GEMM_SMEM (2 * 16384)

__device__ __forceinline__ void load_tile_128x64(
    char* smem, int off, const __half* __restrict__ src, int tid)
{
    #pragma unroll
    for (int it = 0; it < 4; ++it) {
        int i = tid + it * 256;
        int m = i >> 3, q = i & 7;
        uint32_t b = (uint32_t)(m * 128 + q * 16);
        *(uint4*)(smem + off + SW128(b)) = ((const uint4*)(src + m * 64))[q];
    }
}

__global__ __launch_bounds__(256, 2) void mma_gemm_kernel(
    const __half* __restrict__ Af, const __half* __restrict__ Bf,
    float* __restrict__ C)
{
    extern __shared__ char smem[];
    const uint32_t sbase = smem_u32(smem);
    const int tid = threadIdx.x;
    const int wid = tid >> 5, lane = tid & 31;
    const int row0 = blockIdx.y * 128;
    const int col0 = blockIdx.x * 128;

    load_tile_128x64(smem, OFF_AF, Af + (size_t)row0 * R_DIM, tid);
    load_tile_128x64(smem, OFF_BF, Bf + (size_t)col0 * R_DIM, tid);
    __syncthreads();

    const int warp_m = wid & 3;
    const int warp_n = wid >> 2;
    const int mbase = warp_m * 32;
    const int nbase = warp_n * 64;

    const int a_row = mbase + (lane & 15);
    const int a_kb  = (lane >> 4) * 16;
    const int b_nrow = nbase + (lane & 7) + (lane >> 4) * 8;
    const int b_kb   = ((lane >> 3) & 1) * 16;

    float acc[2][8][4];
    #pragma unroll
    for (int mt = 0; mt < 2; ++mt)
        #pragma unroll
        for (int nt = 0; nt < 8; ++nt)
            #pragma unroll
            for (int q = 0; q < 4; ++q) acc[mt][nt][q] = 0.f;

    #pragma unroll
    for (int k = 0; k < 4; ++k) {
        uint32_t a[2][4];
        #pragma unroll
        for (int mt = 0; mt < 2; ++mt) {
            uint32_t b = (uint32_t)((a_row + mt * 16) * 128 + k * 32 + a_kb);
            ldmatrix_x4(a[mt], sbase + OFF_AF + SW128(b));
        }
        uint32_t bf[8][2];
        #pragma unroll
        for (int np = 0; np < 4; ++np) {
            uint32_t b = (uint32_t)((b_nrow + np * 16) * 128 + k * 32 + b_kb);
            uint32_t r[4];
            ldmatrix_x4(r, sbase + OFF_BF + SW128(b));
            bf[np * 2][0] = r[0]; bf[np * 2][1] = r[1];
            bf[np * 2 + 1][0] = r[2]; bf[np * 2 + 1][1] = r[3];
        }
        #pragma unroll
        for (int mt = 0; mt < 2; ++mt)
            #pragma unroll
            for (int nt = 0; nt < 8; ++nt)
                mma_f16(acc[mt][nt], a[mt], bf[nt]);
    }

    const int g = lane >> 2, t = lane & 3;
    #pragma unroll
    for (int mt = 0; mt < 2; ++mt) {
        float* Cr0 = C + (size_t)(row0 + mbase + mt * 16 + g) * D_DIM + col0 + nbase;
        float* Cr1 = Cr0 + 8 * D_DIM;
        #pragma unroll
        for (int nt = 0; nt < 8; ++nt) {
            *(float2*)(Cr0 + nt * 8 + t * 2) =
                make_float2(acc[mt][nt][0], acc[mt][nt][1]);
            *(float2*)(Cr1 + nt * 8 + t * 2) =
                make_float2(acc[mt][nt][2], acc[mt][nt][3]);
        }
    }
}

// ---------------------------------------------------------------------------
extern "C" void kernel_launch(void* const* d_in, const int* in_sizes, int n_in,
                              void* d_out, int out_size)
{
    (void)in_sizes; (void)n_in; (void)out_size;
    const float* U   = (const float*)d_in[0];
    const float* B   = (const float*)d_in[1];
    const float* rsU = (const float*)d_in[2];
    const float* rsB = (const float*)d_in[3];
    const float* cb  = (const float*)d_in[4];
    float* out = (float*)d_out;

    __half *af, *bf;
    cudaGetSymbolAddress((void**)&af, g_Af);
    cudaGetSymbolAddress((void**)&bf, g_Bf);

    cb_prep_kernel<<<8, 256>>>(cb);
    pq_argmin_kernel<<<640, 256>>>(U, B, rsU, rsB, cb, af, bf);

    cudaFuncSetAttribute(mma_gemm_kernel,
                         cudaFuncAttributeMaxDynamicSharedMemorySize, GEMM_SMEM);
    dim3 grid(D_DIM / 128, K_HOT / 128);
    mma_gemm_kernel<<<grid, 256, GEMM_SMEM>>>(af, bf, out);
}